// round 1
// baseline (speedup 1.0000x reference)
#include <cuda_runtime.h>

// Problem shape is fixed: [B=2, D=128, H=160, W=192, C=3] float32 fields.
#define DD 128
#define HH 160
#define WW 192
#define NB 2
#define DHW (DD * HH * WW)          // 3,932,160 voxels per batch
#define TOTAL (NB * DHW)            // 7,864,320 threads

struct f3 { float x, y, z; };

// Trilinear interpolation of vol [D,H,W,3] at absolute coords (fx,fy,fz),
// matching neurite interpn: clip to [0, dim-1], floor/ceil corners,
// ceil index re-clamped, weight of floor corner = loc1 - loc.
__device__ __forceinline__ f3 trilerp(const float* __restrict__ v,
                                      float fx, float fy, float fz) {
    fx = fminf(fmaxf(fx, 0.f), (float)(DD - 1));
    fy = fminf(fmaxf(fy, 0.f), (float)(HH - 1));
    fz = fminf(fmaxf(fz, 0.f), (float)(WW - 1));
    float x0f = floorf(fx), y0f = floorf(fy), z0f = floorf(fz);
    int x0 = (int)x0f, y0 = (int)y0f, z0 = (int)z0f;
    int x1 = min(x0 + 1, DD - 1);
    int y1 = min(y0 + 1, HH - 1);
    int z1 = min(z0 + 1, WW - 1);
    float wx1 = fx - x0f, wy1 = fy - y0f, wz1 = fz - z0f;
    float wx0 = 1.f - wx1, wy0 = 1.f - wy1, wz0 = 1.f - wz1;

    const float* p00 = v + (size_t)((x0 * HH + y0) * WW) * 3;
    const float* p01 = v + (size_t)((x0 * HH + y1) * WW) * 3;
    const float* p10 = v + (size_t)((x1 * HH + y0) * WW) * 3;
    const float* p11 = v + (size_t)((x1 * HH + y1) * WW) * 3;
    int a0 = z0 * 3, a1 = z1 * 3;

    float w00 = wx0 * wy0, w01 = wx0 * wy1;
    float w10 = wx1 * wy0, w11 = wx1 * wy1;

    f3 r;
#define CH(c)                                                              \
    ( w00 * fmaf(wz0, p00[a0 + (c)], wz1 * p00[a1 + (c)])                  \
    + w01 * fmaf(wz0, p01[a0 + (c)], wz1 * p01[a1 + (c)])                  \
    + w10 * fmaf(wz0, p10[a0 + (c)], wz1 * p10[a1 + (c)])                  \
    + w11 * fmaf(wz0, p11[a0 + (c)], wz1 * p11[a1 + (c)]) )
    r.x = CH(0);
    r.y = CH(1);
    r.z = CH(2);
#undef CH
    return r;
}

__global__ __launch_bounds__(256)
void compose_kernel(const float* __restrict__ t1,
                    const float* __restrict__ t2,
                    const float* __restrict__ t3,
                    float* __restrict__ out) {
    int tid = blockIdx.x * blockDim.x + threadIdx.x;
    if (tid >= TOTAL) return;

    int w = tid % WW;
    int t = tid / WW;
    int h = t % HH;
    t /= HH;
    int d = t % DD;
    int b = t / DD;

    const float* v1 = t1 + (size_t)b * DHW * 3;
    const float* v2 = t2 + (size_t)b * DHW * 3;

    size_t i3 = (size_t)tid * 3;
    // s = t3 at this voxel (coherent read)
    float sx = t3[i3 + 0];
    float sy = t3[i3 + 1];
    float sz = t3[i3 + 2];

    // c2 = t3 + warp(t2, t3): gather t2 at grid + s
    f3 g2 = trilerp(v2, (float)d + sx, (float)h + sy, (float)w + sz);
    float cx = sx + g2.x;
    float cy = sy + g2.y;
    float cz = sz + g2.z;

    // out = c2 + warp(t1, c2): gather t1 at grid + c2
    f3 g1 = trilerp(v1, (float)d + cx, (float)h + cy, (float)w + cz);

    out[i3 + 0] = cx + g1.x;
    out[i3 + 1] = cy + g1.y;
    out[i3 + 2] = cz + g1.z;
}

extern "C" void kernel_launch(void* const* d_in, const int* in_sizes, int n_in,
                              void* d_out, int out_size) {
    const float* t1 = (const float*)d_in[0];
    const float* t2 = (const float*)d_in[1];
    const float* t3 = (const float*)d_in[2];
    float* out = (float*)d_out;

    int threads = 256;
    int blocks = (TOTAL + threads - 1) / threads;
    compose_kernel<<<blocks, threads>>>(t1, t2, t3, out);
}